// round 12
// baseline (speedup 1.0000x reference)
#include <cuda_runtime.h>
#include <cuda_bf16.h>
#include <cuda_fp16.h>
#include <cstdint>

#define BATCH 8
#define HWPX  16384
#define EPSV  1e-5f
#define NGRID 296     // 2 CTAs per SM
#define NTILES 2048   // 64-px tiles
#define NT    256

// smem element strides
#define STW1 200   // W1s [96][192] bf16
#define STW2 104   // W2s [192][96] bf16
#define STX  72    // X/H/S region [192][64] (+pad), bf16/fp16

// byte offsets in dynamic smem
#define SM_W1 0                       // 38400
#define SM_W2 38400                   // 39936 -> 78336
#define SM_X  78336                   // 27648 -> 105984 (X rows 0-191; H aliases rows 0-95; S fp16 aliases all)
#define SM_B1 105984                  // 384
#define SM_B2 106368                  // 768
#define SM_XG 107136                  // 6144 -> 113280
#define DSZ   113280

__device__ __forceinline__ uint32_t smem_u32(const void* p) {
    uint32_t a;
    asm("{ .reg .u64 t; cvta.to.shared.u64 t, %1; cvt.u32.u64 %0, t; }" : "=r"(a) : "l"(p));
    return a;
}
__device__ __forceinline__ void ldsm4(uint32_t (&r)[4], uint32_t addr) {
    asm volatile("ldmatrix.sync.aligned.m8n8.x4.shared.b16 {%0,%1,%2,%3}, [%4];"
                 : "=r"(r[0]), "=r"(r[1]), "=r"(r[2]), "=r"(r[3]) : "r"(addr));
}
__device__ __forceinline__ void ldsm2t(uint32_t (&r)[2], uint32_t addr) {
    asm volatile("ldmatrix.sync.aligned.m8n8.x2.trans.shared.b16 {%0,%1}, [%2];"
                 : "=r"(r[0]), "=r"(r[1]) : "r"(addr));
}
__device__ __forceinline__ void mma16816(float (&d)[4], const uint32_t (&a)[4],
                                         const uint32_t (&b)[2]) {
    asm volatile("mma.sync.aligned.m16n8k16.row.col.f32.bf16.bf16.f32 "
                 "{%0,%1,%2,%3}, {%4,%5,%6,%7}, {%8,%9}, {%0,%1,%2,%3};"
                 : "+f"(d[0]), "+f"(d[1]), "+f"(d[2]), "+f"(d[3])
                 : "r"(a[0]), "r"(a[1]), "r"(a[2]), "r"(a[3]), "r"(b[0]), "r"(b[1]));
}
// sigmoid via single-MUFU tanh.approx
__device__ __forceinline__ float sigm(float v) {
    float t;
    asm("tanh.approx.f32 %0, %1;" : "=f"(t) : "f"(0.5f * v));
    return fmaf(0.5f, t, 0.5f);
}
// exp(s), s in (0,1): FMA-only poly
__device__ __forceinline__ float exp01(float s) {
    float u = s - 0.5f;
    float p = 8.3333333e-3f;
    p = fmaf(p, u, 4.1666667e-2f);
    p = fmaf(p, u, 0.16666667f);
    p = fmaf(p, u, 0.5f);
    p = fmaf(p, u, 1.0f);
    p = fmaf(p, u, 1.0f);
    return 1.64872127f * p;
}

__device__ float g_gap[BATCH * 192];
__device__ float g_xg[BATCH * 192];

// ------------------------- GAP (MLP=16) -------------------------
__global__ void gap_kernel(const float* __restrict__ x1, const float* __restrict__ x2,
                           const float* __restrict__ x3) {
    int ch = blockIdx.x, b = blockIdx.y;
    const float* x = (ch < 64) ? x1 : (ch < 128) ? x2 : x3;
    const float* p = x + ((size_t)(b * 64 + (ch & 63))) * HWPX;
    int t4 = threadIdx.x * 4;
    float s0 = 0.f, s1 = 0.f, s2 = 0.f, s3 = 0.f;
#pragma unroll
    for (int i = 0; i < 4; i++) {
        float4 a = *(const float4*)(p + t4 + (i * 4 + 0) * 1024);
        float4 c = *(const float4*)(p + t4 + (i * 4 + 1) * 1024);
        float4 d = *(const float4*)(p + t4 + (i * 4 + 2) * 1024);
        float4 e = *(const float4*)(p + t4 + (i * 4 + 3) * 1024);
        s0 += (a.x + a.y) + (a.z + a.w);
        s1 += (c.x + c.y) + (c.z + c.w);
        s2 += (d.x + d.y) + (d.z + d.w);
        s3 += (e.x + e.y) + (e.z + e.w);
    }
    float s = (s0 + s1) + (s2 + s3);
#pragma unroll
    for (int off = 16; off; off >>= 1) s += __shfl_down_sync(0xFFFFFFFFu, s, off);
    __shared__ float sm[8];
    if ((threadIdx.x & 31) == 0) sm[threadIdx.x >> 5] = s;
    __syncthreads();
    if (threadIdx.x == 0) {
        float t = 0.f;
#pragma unroll
        for (int w = 0; w < 8; w++) t += sm[w];
        g_gap[b * 192 + ch] = t * (1.f / (float)HWPX);
    }
}

// ------------------------- global-branch MLP -------------------------
__global__ void gmlp_kernel(const float* __restrict__ gw1, const float* __restrict__ gb1,
                            const float* __restrict__ gg1, const float* __restrict__ gbe1,
                            const float* __restrict__ gm1, const float* __restrict__ gv1,
                            const float* __restrict__ gw2, const float* __restrict__ gb2,
                            const float* __restrict__ gg2, const float* __restrict__ gbe2,
                            const float* __restrict__ gm2, const float* __restrict__ gv2) {
    int b = blockIdx.x, t = threadIdx.x;
    __shared__ float v[192], h[96];
    v[t] = g_gap[b * 192 + t];
    __syncthreads();
    if (t < 96) {
        float a = gb1[t];
        const float* w = gw1 + t * 192;
#pragma unroll 4
        for (int c = 0; c < 192; c++) a = fmaf(w[c], v[c], a);
        float s = gg1[t] * rsqrtf(gv1[t] + EPSV);
        h[t] = fmaxf(fmaf(a - gm1[t], s, gbe1[t]), 0.f);
    }
    __syncthreads();
    {
        float a = gb2[t];
        const float* w = gw2 + t * 96;
#pragma unroll 4
        for (int c = 0; c < 96; c++) a = fmaf(w[c], h[c], a);
        float s = gg2[t] * rsqrtf(gv2[t] + EPSV);
        g_xg[b * 192 + t] = fmaf(a - gm2[t], s, gbe2[t]);
    }
}

// ---------- fused main kernel: 256 thr, 64-px tiles, X/H/S aliased, 2 CTAs/SM ----------
__global__ __launch_bounds__(NT, 2)
void main_kernel(const float* __restrict__ x1, const float* __restrict__ x2,
                 const float* __restrict__ x3,
                 const float* __restrict__ lw1, const float* __restrict__ lb1,
                 const float* __restrict__ lg1, const float* __restrict__ lbe1,
                 const float* __restrict__ lm1, const float* __restrict__ lv1,
                 const float* __restrict__ lw2, const float* __restrict__ lb2,
                 const float* __restrict__ lg2, const float* __restrict__ lbe2,
                 const float* __restrict__ lm2, const float* __restrict__ lv2,
                 float* __restrict__ out) {
    extern __shared__ char dsm[];
    const uint32_t SB = smem_u32(dsm);

    int tid = threadIdx.x;
    int wid = tid >> 5, lane = tid & 31;
    int qrow = lane >> 2;          // 0..7
    int qcol = lane & 3;           // 0..3
    int lsrow = lane & 15;
    int lscol = (lane >> 4) << 3;
    int s4 = wid & 3;              // px strip 0..3 (16 px each)
    int g  = wid >> 2;             // channel group 0..1
    int n0 = s4 << 4;

    int pq = tid & 15;             // pixel quad index (combine/load layout)
    int chb = tid >> 4;            // 0..15
    int px = pq << 2;

    float* B1s = (float*)(dsm + SM_B1);
    float* B2s = (float*)(dsm + SM_B2);
    float* XGs = (float*)(dsm + SM_XG);

    // ---- prologue: fold BN into bf16 weights ----
    for (int i = tid; i < 96 * 192; i += NT) {
        int o = i / 192, k = i - o * 192;
        float sc = lg1[o] * rsqrtf(lv1[o] + EPSV);
        *(__nv_bfloat16*)(dsm + SM_W1 + (o * STW1 + k) * 2) = __float2bfloat16_rn(lw1[i] * sc);
        if (k == 0) B1s[o] = fmaf(lb1[o] - lm1[o], sc, lbe1[o]);
    }
    for (int i = tid; i < 192 * 96; i += NT) {
        int o = i / 96, k = i - o * 96;
        float sc = lg2[o] * rsqrtf(lv2[o] + EPSV);
        *(__nv_bfloat16*)(dsm + SM_W2 + (o * STW2 + k) * 2) = __float2bfloat16_rn(lw2[i] * sc);
        if (k == 0) B2s[o] = fmaf(lb2[o] - lm2[o], sc, lbe2[o]);
    }
    __syncthreads();
    for (int i = tid; i < BATCH * 192; i += NT) {
        int bb = i / 192;
        int c = i - bb * 192;
        XGs[i] = B2s[c] + g_xg[i];
    }
    __syncthreads();

    const uint32_t W1S = SB + SM_W1, W2S = SB + SM_W2, XS = SB + SM_X;

    for (int T = blockIdx.x; T < NTILES; T += NGRID) {
        int b = T >> 8;
        int hw0 = (T & 255) << 6;
        const float* XGb = XGs + b * 192;

        // ---- load X tile [192 ch][64 px] -> bf16 smem (coalesced LDG.128) ----
#pragma unroll
        for (int j = 0; j < 12; j++) {
            int ch = chb + 16 * j;
            const float* xp = (ch < 64) ? x1 : (ch < 128) ? x2 : x3;
            float4 v = *(const float4*)(xp + ((size_t)((b << 6) + (ch & 63))) * HWPX + hw0 + px);
            __nv_bfloat162 p0 = __floats2bfloat162_rn(v.x, v.y);
            __nv_bfloat162 p1 = __floats2bfloat162_rn(v.z, v.w);
            *(uint2*)(dsm + SM_X + (ch * STX + px) * 2) =
                make_uint2(*(uint32_t*)&p0, *(uint32_t*)&p1);
        }
        __syncthreads();

        // ---- GEMM1: warp (s4,g): C1[48ch of group g][16px strip], K=192 ----
        float acc1[3][2][4];
#pragma unroll
        for (int mi = 0; mi < 3; mi++)
#pragma unroll
            for (int nf = 0; nf < 2; nf++)
#pragma unroll
                for (int i = 0; i < 4; i++) acc1[mi][nf][i] = 0.f;
#pragma unroll
        for (int kt = 0; kt < 12; kt++) {
            uint32_t b0[2], b1[2];
            ldsm2t(b0, XS + ((16 * kt + lsrow) * STX + n0) * 2);
            ldsm2t(b1, XS + ((16 * kt + lsrow) * STX + n0 + 8) * 2);
#pragma unroll
            for (int mi = 0; mi < 3; mi++) {
                uint32_t a[4];
                ldsm4(a, W1S + ((16 * (3 * g + mi) + lsrow) * STW1 + 16 * kt + lscol) * 2);
                mma16816(acc1[mi][0], a, b0);
                mma16816(acc1[mi][1], a, b1);
            }
        }
        // pair barrier A: both pair warps finished reading X strip (H will alias it)
        asm volatile("bar.sync %0, %1;" :: "r"(s4 + 1), "r"(64) : "memory");

        // ---- epilogue1: bias + relu -> H (rows 0-95, ALIASES X rows 0-95, strip cols) ----
#pragma unroll
        for (int mi = 0; mi < 3; mi++) {
            int ca = 16 * (3 * g + mi) + qrow;
            float ba = B1s[ca], bb = B1s[ca + 8];
#pragma unroll
            for (int nf = 0; nf < 2; nf++) {
                int pxb = n0 + 8 * nf + 2 * qcol;
                __nv_bfloat162 ha = __floats2bfloat162_rn(fmaxf(acc1[mi][nf][0] + ba, 0.f),
                                                          fmaxf(acc1[mi][nf][1] + ba, 0.f));
                __nv_bfloat162 hb = __floats2bfloat162_rn(fmaxf(acc1[mi][nf][2] + bb, 0.f),
                                                          fmaxf(acc1[mi][nf][3] + bb, 0.f));
                *(uint32_t*)(dsm + SM_X + (ca * STX + pxb) * 2) = *(uint32_t*)&ha;
                *(uint32_t*)(dsm + SM_X + ((ca + 8) * STX + pxb) * 2) = *(uint32_t*)&hb;
            }
        }
        // pair barrier B: H strip complete
        asm volatile("bar.sync %0, %1;" :: "r"(s4 + 1), "r"(64) : "memory");

        // ---- GEMM2: warp (s4,g): 6 m-tiles (2 triples), K=96, B from H(=X rows 0-95) ----
        float acc2[6][2][4];
#pragma unroll
        for (int i6 = 0; i6 < 6; i6++)
#pragma unroll
            for (int nf = 0; nf < 2; nf++)
#pragma unroll
                for (int i = 0; i < 4; i++) acc2[i6][nf][i] = 0.f;
#pragma unroll
        for (int kt = 0; kt < 6; kt++) {
            uint32_t h0[2], h1[2];
            ldsm2t(h0, XS + ((16 * kt + lsrow) * STX + n0) * 2);
            ldsm2t(h1, XS + ((16 * kt + lsrow) * STX + n0 + 8) * 2);
#pragma unroll
            for (int i6 = 0; i6 < 6; i6++) {
                int mt = 4 * (i6 >> 1) + 2 * g + (i6 & 1);
                uint32_t a[4];
                ldsm4(a, W2S + ((16 * mt + lsrow) * STW2 + 16 * kt + lscol) * 2);
                mma16816(acc2[i6][0], a, h0);
                mma16816(acc2[i6][1], a, h1);
            }
        }
        // pair barrier C: both pair warps finished reading H strip (S will alias it)
        asm volatile("bar.sync %0, %1;" :: "r"(s4 + 1), "r"(64) : "memory");

        // ---- prefetch x for combine (coalesced, L2-resident) ----
        float4 xv[12];
#pragma unroll
        for (int j = 0; j < 12; j++) {
            int ch = chb + 16 * j;
            const float* xp = (ch < 64) ? x1 : (ch < 128) ? x2 : x3;
            xv[j] = *(const float4*)(xp + ((size_t)((b << 6) + (ch & 63))) * HWPX + hw0 + px);
        }

        // ---- epilogue2: sigmoid -> S fp16 (ALIASES X/H region, strip cols) ----
#pragma unroll
        for (int i6 = 0; i6 < 6; i6++) {
            int grp = i6 >> 1, tt = i6 & 1;
#pragma unroll
            for (int j = 0; j < 2; j++) {
                int cf = 64 * grp + 32 * g + 16 * tt + 8 * j + qrow;
                float base = XGb[cf];
#pragma unroll
                for (int nf = 0; nf < 2; nf++) {
                    int pxb = n0 + 8 * nf + 2 * qcol;
                    __half2 hv = __floats2half2_rn(sigm(acc2[i6][nf][2 * j] + base),
                                                   sigm(acc2[i6][nf][2 * j + 1] + base));
                    *(__half2*)(dsm + SM_X + (cf * STX + pxb) * 2) = hv;
                }
            }
        }
        __syncthreads();

        // ---- combine: x from regs, S from smem, coalesced float4 STG ----
#pragma unroll
        for (int a = 0; a < 4; a++) {
            int c = chb + 16 * a;   // 0..63
            uint2 rA = *(const uint2*)(dsm + SM_X + (c * STX + px) * 2);
            uint2 rB = *(const uint2*)(dsm + SM_X + ((c + 64) * STX + px) * 2);
            uint2 rC = *(const uint2*)(dsm + SM_X + ((c + 128) * STX + px) * 2);
            float2 a01 = __half22float2(*(__half2*)&rA.x);
            float2 a23 = __half22float2(*(__half2*)&rA.y);
            float2 b01 = __half22float2(*(__half2*)&rB.x);
            float2 b23 = __half22float2(*(__half2*)&rB.y);
            float2 c01 = __half22float2(*(__half2*)&rC.x);
            float2 c23 = __half22float2(*(__half2*)&rC.y);
            float sa[4] = {a01.x, a01.y, a23.x, a23.y};
            float sb[4] = {b01.x, b01.y, b23.x, b23.y};
            float sc[4] = {c01.x, c01.y, c23.x, c23.y};
            float xa[4] = {xv[a].x, xv[a].y, xv[a].z, xv[a].w};
            float xb[4] = {xv[a + 4].x, xv[a + 4].y, xv[a + 4].z, xv[a + 4].w};
            float xc[4] = {xv[a + 8].x, xv[a + 8].y, xv[a + 8].z, xv[a + 8].w};
            float r[4];
#pragma unroll
            for (int k = 0; k < 4; k++) {
                float e0 = exp01(sa[k]), e1 = exp01(sb[k]), e2 = exp01(sc[k]);
                float inv = __fdividef(1.f, e0 + e1 + e2);
                r[k] = (e0 * xa[k] + e1 * xb[k] + e2 * xc[k]) * inv;
            }
            *(float4*)(out + ((size_t)((b << 6) + c)) * HWPX + hw0 + px) =
                make_float4(r[0], r[1], r[2], r[3]);
        }
        __syncthreads();
    }
}

extern "C" void kernel_launch(void* const* d_in, const int* in_sizes, int n_in,
                              void* d_out, int out_size) {
    const float* x1 = (const float*)d_in[0];
    const float* x2 = (const float*)d_in[1];
    const float* x3 = (const float*)d_in[2];
    const float* lw1 = (const float*)d_in[3];
    const float* lb1 = (const float*)d_in[4];
    const float* lg1 = (const float*)d_in[5];
    const float* lbe1 = (const float*)d_in[6];
    const float* lm1 = (const float*)d_in[7];
    const float* lv1 = (const float*)d_in[8];
    const float* lw2 = (const float*)d_in[9];
    const float* lb2 = (const float*)d_in[10];
    const float* lg2 = (const float*)d_in[11];
    const float* lbe2 = (const float*)d_in[12];
    const float* lm2 = (const float*)d_in[13];
    const float* lv2 = (const float*)d_in[14];
    const float* gw1 = (const float*)d_in[15];
    const float* gb1 = (const float*)d_in[16];
    const float* gg1 = (const float*)d_in[17];
    const float* gbe1 = (const float*)d_in[18];
    const float* gm1 = (const float*)d_in[19];
    const float* gv1 = (const float*)d_in[20];
    const float* gw2 = (const float*)d_in[21];
    const float* gb2 = (const float*)d_in[22];
    const float* gg2 = (const float*)d_in[23];
    const float* gbe2 = (const float*)d_in[24];
    const float* gm2 = (const float*)d_in[25];
    const float* gv2 = (const float*)d_in[26];
    float* out = (float*)d_out;

    cudaFuncSetAttribute(main_kernel, cudaFuncAttributeMaxDynamicSharedMemorySize, DSZ);

    gap_kernel<<<dim3(192, BATCH), 256>>>(x1, x2, x3);
    gmlp_kernel<<<BATCH, 192>>>(gw1, gb1, gg1, gbe1, gm1, gv1,
                                gw2, gb2, gg2, gbe2, gm2, gv2);
    main_kernel<<<NGRID, NT, DSZ>>>(x1, x2, x3,
                                    lw1, lb1, lg1, lbe1, lm1, lv1,
                                    lw2, lb2, lg2, lbe2, lm2, lv2, out);
}

// round 13
// speedup vs baseline: 1.0669x; 1.0669x over previous
#include <cuda_runtime.h>
#include <cuda_bf16.h>
#include <cuda_fp16.h>
#include <cstdint>

#define BATCH 8
#define HWPX  16384
#define EPSV  1e-5f
#define NCTA  148
#define NTILES 1024   // 128-px tiles
#define NT    512

// smem element strides
#define STW1 200   // W1s [96][192] bf16
#define STW2 104   // W2s [192][96] bf16
#define STX  136   // X bufs [192][128] bf16; also S fp16 stride (aliased)
#define STH  136   // Hs [96][128] bf16

// byte offsets in dynamic smem
#define SM_W1 0                       // 38400
#define SM_W2 38400                   // -> 78336
#define SM_X0 78336                   // 52224 -> 130560
#define SM_X1 130560                  // 52224 -> 182784
#define SM_H  182784                  // 26112 -> 208896
#define SM_B1 208896                  // 384
#define SM_B2 209280                  // 768
#define SM_XG 210048                  // 6144 -> 216192
#define DSZ   216192

__device__ __forceinline__ uint32_t smem_u32(const void* p) {
    uint32_t a;
    asm("{ .reg .u64 t; cvta.to.shared.u64 t, %1; cvt.u32.u64 %0, t; }" : "=r"(a) : "l"(p));
    return a;
}
__device__ __forceinline__ void ldsm4(uint32_t (&r)[4], uint32_t addr) {
    asm volatile("ldmatrix.sync.aligned.m8n8.x4.shared.b16 {%0,%1,%2,%3}, [%4];"
                 : "=r"(r[0]), "=r"(r[1]), "=r"(r[2]), "=r"(r[3]) : "r"(addr));
}
// x4 transposed: lanes 0-15 rows at px base, lanes 16-31 rows at px base+8
__device__ __forceinline__ void ldsm4t(uint32_t (&r)[4], uint32_t addr) {
    asm volatile("ldmatrix.sync.aligned.m8n8.x4.trans.shared.b16 {%0,%1,%2,%3}, [%4];"
                 : "=r"(r[0]), "=r"(r[1]), "=r"(r[2]), "=r"(r[3]) : "r"(addr));
}
__device__ __forceinline__ void mma16816(float (&d)[4], const uint32_t (&a)[4],
                                         const uint32_t* b) {
    asm volatile("mma.sync.aligned.m16n8k16.row.col.f32.bf16.bf16.f32 "
                 "{%0,%1,%2,%3}, {%4,%5,%6,%7}, {%8,%9}, {%0,%1,%2,%3};"
                 : "+f"(d[0]), "+f"(d[1]), "+f"(d[2]), "+f"(d[3])
                 : "r"(a[0]), "r"(a[1]), "r"(a[2]), "r"(a[3]), "r"(b[0]), "r"(b[1]));
}
// sigmoid via single-MUFU tanh.approx: sigm(v) = 0.5 + 0.5*tanh(v/2)
__device__ __forceinline__ float sigm(float v) {
    float t;
    asm("tanh.approx.f32 %0, %1;" : "=f"(t) : "f"(0.5f * v));
    return fmaf(0.5f, t, 0.5f);
}
// exp(s), s in (0,1): e^0.5 * Taylor(u=s-0.5), rel err < 2e-5, FMA-only
__device__ __forceinline__ float exp01(float s) {
    float u = s - 0.5f;
    float p = 8.3333333e-3f;
    p = fmaf(p, u, 4.1666667e-2f);
    p = fmaf(p, u, 0.16666667f);
    p = fmaf(p, u, 0.5f);
    p = fmaf(p, u, 1.0f);
    p = fmaf(p, u, 1.0f);
    return 1.64872127f * p;
}

__device__ float g_gap[BATCH * 192];
__device__ float g_xg[BATCH * 192];

// ------------------------- GAP (MLP=16) -------------------------
__global__ void gap_kernel(const float* __restrict__ x1, const float* __restrict__ x2,
                           const float* __restrict__ x3) {
    int ch = blockIdx.x, b = blockIdx.y;
    const float* x = (ch < 64) ? x1 : (ch < 128) ? x2 : x3;
    const float* p = x + ((size_t)(b * 64 + (ch & 63))) * HWPX;
    int t4 = threadIdx.x * 4;
    float s0 = 0.f, s1 = 0.f, s2 = 0.f, s3 = 0.f;
#pragma unroll
    for (int i = 0; i < 4; i++) {
        float4 a = *(const float4*)(p + t4 + (i * 4 + 0) * 1024);
        float4 c = *(const float4*)(p + t4 + (i * 4 + 1) * 1024);
        float4 d = *(const float4*)(p + t4 + (i * 4 + 2) * 1024);
        float4 e = *(const float4*)(p + t4 + (i * 4 + 3) * 1024);
        s0 += (a.x + a.y) + (a.z + a.w);
        s1 += (c.x + c.y) + (c.z + c.w);
        s2 += (d.x + d.y) + (d.z + d.w);
        s3 += (e.x + e.y) + (e.z + e.w);
    }
    float s = (s0 + s1) + (s2 + s3);
#pragma unroll
    for (int off = 16; off; off >>= 1) s += __shfl_down_sync(0xFFFFFFFFu, s, off);
    __shared__ float sm[8];
    if ((threadIdx.x & 31) == 0) sm[threadIdx.x >> 5] = s;
    __syncthreads();
    if (threadIdx.x == 0) {
        float t = 0.f;
#pragma unroll
        for (int w = 0; w < 8; w++) t += sm[w];
        g_gap[b * 192 + ch] = t * (1.f / (float)HWPX);
    }
}

// ------------------------- global-branch MLP -------------------------
__global__ void gmlp_kernel(const float* __restrict__ gw1, const float* __restrict__ gb1,
                            const float* __restrict__ gg1, const float* __restrict__ gbe1,
                            const float* __restrict__ gm1, const float* __restrict__ gv1,
                            const float* __restrict__ gw2, const float* __restrict__ gb2,
                            const float* __restrict__ gg2, const float* __restrict__ gbe2,
                            const float* __restrict__ gm2, const float* __restrict__ gv2) {
    int b = blockIdx.x, t = threadIdx.x;
    __shared__ float v[192], h[96];
    v[t] = g_gap[b * 192 + t];
    __syncthreads();
    if (t < 96) {
        float a = gb1[t];
        const float* w = gw1 + t * 192;
#pragma unroll 4
        for (int c = 0; c < 192; c++) a = fmaf(w[c], v[c], a);
        float s = gg1[t] * rsqrtf(gv1[t] + EPSV);
        h[t] = fmaxf(fmaf(a - gm1[t], s, gbe1[t]), 0.f);
    }
    __syncthreads();
    {
        float a = gb2[t];
        const float* w = gw2 + t * 96;
#pragma unroll 4
        for (int c = 0; c < 96; c++) a = fmaf(w[c], h[c], a);
        float s = gg2[t] * rsqrtf(gv2[t] + EPSV);
        g_xg[b * 192 + t] = fmaf(a - gm2[t], s, gbe2[t]);
    }
}

// ------------------------- fused main kernel: 512 thr, 128-px tiles, X double-buffer ----
__global__ __launch_bounds__(NT, 1)
void main_kernel(const float* __restrict__ x1, const float* __restrict__ x2,
                 const float* __restrict__ x3,
                 const float* __restrict__ lw1, const float* __restrict__ lb1,
                 const float* __restrict__ lg1, const float* __restrict__ lbe1,
                 const float* __restrict__ lm1, const float* __restrict__ lv1,
                 const float* __restrict__ lw2, const float* __restrict__ lb2,
                 const float* __restrict__ lg2, const float* __restrict__ lbe2,
                 const float* __restrict__ lm2, const float* __restrict__ lv2,
                 float* __restrict__ out) {
    extern __shared__ char dsm[];
    const uint32_t SB = smem_u32(dsm);

    int tid = threadIdx.x;
    int wid = tid >> 5, lane = tid & 31;
    int qrow = lane >> 2;          // 0..7
    int qcol = lane & 3;           // 0..3
    int lsrow = lane & 15;
    int lscol = (lane >> 4) << 3;
    int s8 = wid & 7;              // px strip 0..7 (16 px each)
    int g  = wid >> 3;             // channel group 0..1
    int n0 = s8 << 4;
    int bofs = (lane >> 4) << 3;   // x4.trans px sub-offset (0 or 8)

    float* B1s = (float*)(dsm + SM_B1);
    float* B2s = (float*)(dsm + SM_B2);
    float* XGs = (float*)(dsm + SM_XG);

    // ---- prologue: fold BN into bf16 weights ----
    for (int i = tid; i < 96 * 192; i += NT) {
        int o = i / 192, k = i - o * 192;
        float sc = lg1[o] * rsqrtf(lv1[o] + EPSV);
        *(__nv_bfloat16*)(dsm + SM_W1 + (o * STW1 + k) * 2) = __float2bfloat16_rn(lw1[i] * sc);
        if (k == 0) B1s[o] = fmaf(lb1[o] - lm1[o], sc, lbe1[o]);
    }
    for (int i = tid; i < 192 * 96; i += NT) {
        int o = i / 96, k = i - o * 96;
        float sc = lg2[o] * rsqrtf(lv2[o] + EPSV);
        *(__nv_bfloat16*)(dsm + SM_W2 + (o * STW2 + k) * 2) = __float2bfloat16_rn(lw2[i] * sc);
        if (k == 0) B2s[o] = fmaf(lb2[o] - lm2[o], sc, lbe2[o]);
    }
    __syncthreads();
    for (int i = tid; i < BATCH * 192; i += NT) {
        int bb = i / 192;
        int c = i - bb * 192;
        XGs[i] = B2s[c] + g_xg[i];
    }

    const uint32_t W1S = SB + SM_W1, W2S = SB + SM_W2, HS = SB + SM_H;
    int px = lane << 2;   // this thread's pixel quad

    // ---- preload first tile into buffer 0 ----
    {
        int T0 = blockIdx.x;
        int b0 = T0 >> 7, hw00 = (T0 & 127) << 7;
#pragma unroll
        for (int j = 0; j < 12; j++) {
            int ch = wid + 16 * j;
            const float* xp = (ch < 64) ? x1 : (ch < 128) ? x2 : x3;
            float4 v = *(const float4*)(xp + ((size_t)((b0 << 6) + (ch & 63))) * HWPX + hw00 + px);
            __nv_bfloat162 p0 = __floats2bfloat162_rn(v.x, v.y);
            __nv_bfloat162 p1 = __floats2bfloat162_rn(v.z, v.w);
            *(uint2*)(dsm + SM_X0 + (ch * STX + px) * 2) =
                make_uint2(*(uint32_t*)&p0, *(uint32_t*)&p1);
        }
    }
    __syncthreads();

    int p = 0;
    for (int T = blockIdx.x; T < NTILES; T += NCTA) {
        int b = T >> 7;
        int hw0 = (T & 127) << 7;
        const float* XGb = XGs + b * 192;
        const uint32_t xoff  = p ? SM_X1 : SM_X0;
        const uint32_t xoffn = p ? SM_X0 : SM_X1;
        const uint32_t XS = SB + xoff;

        // ---- prefetch NEXT tile's X into regs (latency hidden by GEMM1) ----
        int Tn = T + NCTA;
        bool hasNext = Tn < NTILES;
        int Tc = hasNext ? Tn : T;
        int bn = Tc >> 7, hwn = (Tc & 127) << 7;
        float4 xn[12];
#pragma unroll
        for (int j = 0; j < 12; j++) {
            int ch = wid + 16 * j;
            const float* xp = (ch < 64) ? x1 : (ch < 128) ? x2 : x3;
            xn[j] = *(const float4*)(xp + ((size_t)((bn << 6) + (ch & 63))) * HWPX + hwn + px);
        }

        // ---- GEMM1: warp (s8,g): C1[48ch of group g][16px strip], K=192 ----
        float acc1[3][2][4];
#pragma unroll
        for (int mi = 0; mi < 3; mi++)
#pragma unroll
            for (int nf = 0; nf < 2; nf++)
#pragma unroll
                for (int i = 0; i < 4; i++) acc1[mi][nf][i] = 0.f;
#pragma unroll
        for (int kt = 0; kt < 12; kt++) {
            uint32_t bf[4];   // {b0[0],b0[1],b1[0],b1[1]} via one x4.trans
            ldsm4t(bf, XS + ((16 * kt + lsrow) * STX + n0 + bofs) * 2);
#pragma unroll
            for (int mi = 0; mi < 3; mi++) {
                uint32_t a[4];
                ldsm4(a, W1S + ((16 * (3 * g + mi) + lsrow) * STW1 + 16 * kt + lscol) * 2);
                mma16816(acc1[mi][0], a, bf);
                mma16816(acc1[mi][1], a, bf + 2);
            }
        }

        // ---- epilogue1: bias + relu -> Hs (strip-local) ----
#pragma unroll
        for (int mi = 0; mi < 3; mi++) {
            int ca = 16 * (3 * g + mi) + qrow;
            float ba = B1s[ca], bb = B1s[ca + 8];
#pragma unroll
            for (int nf = 0; nf < 2; nf++) {
                int pxb = n0 + 8 * nf + 2 * qcol;
                __nv_bfloat162 ha = __floats2bfloat162_rn(fmaxf(acc1[mi][nf][0] + ba, 0.f),
                                                          fmaxf(acc1[mi][nf][1] + ba, 0.f));
                __nv_bfloat162 hb = __floats2bfloat162_rn(fmaxf(acc1[mi][nf][2] + bb, 0.f),
                                                          fmaxf(acc1[mi][nf][3] + bb, 0.f));
                *(uint32_t*)(dsm + SM_H + (ca * STH + pxb) * 2) = *(uint32_t*)&ha;
                *(uint32_t*)(dsm + SM_H + ((ca + 8) * STH + pxb) * 2) = *(uint32_t*)&hb;
            }
        }

        // ---- store prefetched next tile into the dead alternate buffer ----
        if (hasNext) {
#pragma unroll
            for (int j = 0; j < 12; j++) {
                int ch = wid + 16 * j;
                __nv_bfloat162 p0 = __floats2bfloat162_rn(xn[j].x, xn[j].y);
                __nv_bfloat162 p1 = __floats2bfloat162_rn(xn[j].z, xn[j].w);
                *(uint2*)(dsm + xoffn + (ch * STX + px) * 2) =
                    make_uint2(*(uint32_t*)&p0, *(uint32_t*)&p1);
            }
        }

        // pair barrier: H strip s8 produced/consumed only by warps (s8,0),(s8,1)
        asm volatile("bar.sync %0, %1;" :: "r"(s8 + 1), "r"(64) : "memory");

        // ---- GEMM2: warp (s8,g): 6 m-tiles (triples of [32g,32g+32)), K=96 ----
        float acc2[6][2][4];
#pragma unroll
        for (int i6 = 0; i6 < 6; i6++)
#pragma unroll
            for (int nf = 0; nf < 2; nf++)
#pragma unroll
                for (int i = 0; i < 4; i++) acc2[i6][nf][i] = 0.f;
#pragma unroll
        for (int kt = 0; kt < 6; kt++) {
            uint32_t hf[4];
            ldsm4t(hf, HS + ((16 * kt + lsrow) * STH + n0 + bofs) * 2);
#pragma unroll
            for (int i6 = 0; i6 < 6; i6++) {
                int mt = 4 * (i6 >> 1) + 2 * g + (i6 & 1);
                uint32_t a[4];
                ldsm4(a, W2S + ((16 * mt + lsrow) * STW2 + 16 * kt + lscol) * 2);
                mma16816(acc2[i6][0], a, hf);
                mma16816(acc2[i6][1], a, hf + 2);
            }
        }

        // ---- prefetch current-tile x for combine (coalesced, L2-resident) ----
        float4 xv[12];
#pragma unroll
        for (int j = 0; j < 12; j++) {
            int ch = wid + 16 * j;
            const float* xp = (ch < 64) ? x1 : (ch < 128) ? x2 : x3;
            xv[j] = *(const float4*)(xp + ((size_t)((b << 6) + (ch & 63))) * HWPX + hw0 + px);
        }

        // ---- epilogue2: sigmoid -> S fp16 (aliases CURRENT X buf, strip-local cols) ----
#pragma unroll
        for (int i6 = 0; i6 < 6; i6++) {
            int grp = i6 >> 1, tt = i6 & 1;
#pragma unroll
            for (int j = 0; j < 2; j++) {
                int cf = 64 * grp + 32 * g + 16 * tt + 8 * j + qrow;
                float base = XGb[cf];
#pragma unroll
                for (int nf = 0; nf < 2; nf++) {
                    int pxb = n0 + 8 * nf + 2 * qcol;
                    __half2 hv = __floats2half2_rn(sigm(acc2[i6][nf][2 * j] + base),
                                                   sigm(acc2[i6][nf][2 * j + 1] + base));
                    *(__half2*)(dsm + xoff + (cf * STX + pxb) * 2) = hv;
                }
            }
        }
        __syncthreads();

        // ---- combine: x from prefetched regs, S from smem, coalesced float4 STG ----
#pragma unroll
        for (int a = 0; a < 4; a++) {
            int c = wid + 16 * a;   // 0..63
            uint2 rA = *(const uint2*)(dsm + xoff + (c * STX + px) * 2);
            uint2 rB = *(const uint2*)(dsm + xoff + ((c + 64) * STX + px) * 2);
            uint2 rC = *(const uint2*)(dsm + xoff + ((c + 128) * STX + px) * 2);
            float2 a01 = __half22float2(*(__half2*)&rA.x);
            float2 a23 = __half22float2(*(__half2*)&rA.y);
            float2 b01 = __half22float2(*(__half2*)&rB.x);
            float2 b23 = __half22float2(*(__half2*)&rB.y);
            float2 c01 = __half22float2(*(__half2*)&rC.x);
            float2 c23 = __half22float2(*(__half2*)&rC.y);
            float sa[4] = {a01.x, a01.y, a23.x, a23.y};
            float sb[4] = {b01.x, b01.y, b23.x, b23.y};
            float sc[4] = {c01.x, c01.y, c23.x, c23.y};
            float xa[4] = {xv[a].x, xv[a].y, xv[a].z, xv[a].w};
            float xb[4] = {xv[a + 4].x, xv[a + 4].y, xv[a + 4].z, xv[a + 4].w};
            float xc[4] = {xv[a + 8].x, xv[a + 8].y, xv[a + 8].z, xv[a + 8].w};
            float r[4];
#pragma unroll
            for (int k = 0; k < 4; k++) {
                float e0 = exp01(sa[k]), e1 = exp01(sb[k]), e2 = exp01(sc[k]);
                float inv = __fdividef(1.f, e0 + e1 + e2);
                r[k] = (e0 * xa[k] + e1 * xb[k] + e2 * xc[k]) * inv;
            }
            *(float4*)(out + ((size_t)((b << 6) + c)) * HWPX + hw0 + px) =
                make_float4(r[0], r[1], r[2], r[3]);
        }
        __syncthreads();
        p ^= 1;
    }
}

extern "C" void kernel_launch(void* const* d_in, const int* in_sizes, int n_in,
                              void* d_out, int out_size) {
    const float* x1 = (const float*)d_in[0];
    const float* x2 = (const float*)d_in[1];
    const float* x3 = (const float*)d_in[2];
    const float* lw1 = (const float*)d_in[3];
    const float* lb1 = (const float*)d_in[4];
    const float* lg1 = (const float*)d_in[5];
    const float* lbe1 = (const float*)d_in[6];
    const float* lm1 = (const float*)d_in[7];
    const float* lv1 = (const float*)d_in[8];
    const float* lw2 = (const float*)d_in[9];
    const float* lb2 = (const float*)d_in[10];
    const float* lg2 = (const float*)d_in[11];
    const float* lbe2 = (const float*)d_in[12];
    const float* lm2 = (const float*)d_in[13];
    const float* lv2 = (const float*)d_in[14];
    const float* gw1 = (const float*)d_in[15];
    const float* gb1 = (const float*)d_in[16];
    const float* gg1 = (const float*)d_in[17];
    const float* gbe1 = (const float*)d_in[18];
    const float* gm1 = (const float*)d_in[19];
    const float* gv1 = (const float*)d_in[20];
    const float* gw2 = (const float*)d_in[21];
    const float* gb2 = (const float*)d_in[22];
    const float* gg2 = (const float*)d_in[23];
    const float* gbe2 = (const float*)d_in[24];
    const float* gm2 = (const float*)d_in[25];
    const float* gv2 = (const float*)d_in[26];
    float* out = (float*)d_out;

    cudaFuncSetAttribute(main_kernel, cudaFuncAttributeMaxDynamicSharedMemorySize, DSZ);

    gap_kernel<<<dim3(192, BATCH), 256>>>(x1, x2, x3);
    gmlp_kernel<<<BATCH, 192>>>(gw1, gb1, gg1, gbe1, gm1, gv1,
                                gw2, gb2, gg2, gbe2, gm2, gv2);
    main_kernel<<<NCTA, NT, DSZ>>>(x1, x2, x3,
                                   lw1, lb1, lg1, lbe1, lm1, lv1,
                                   lw2, lb2, lg2, lbe2, lm2, lv2, out);
}

// round 14
// speedup vs baseline: 1.0858x; 1.0178x over previous
#include <cuda_runtime.h>
#include <cuda_bf16.h>
#include <cuda_fp16.h>
#include <cstdint>

#define BATCH 8
#define HWPX  16384
#define EPSV  1e-5f
#define NCTA  148
#define NTILES 1024   // 128-px tiles
#define NT    512

// smem element strides
#define STW1 200   // W1s [96][192] bf16
#define STW2 104   // W2s [192][96] bf16
#define STX  136   // X bufs [192][128] bf16; also S fp16 stride (aliased)
#define STH  136   // Hs [96][128] bf16

// byte offsets in dynamic smem
#define SM_W1 0                       // 38400
#define SM_W2 38400                   // -> 78336
#define SM_X0 78336                   // 52224 -> 130560
#define SM_X1 130560                  // 52224 -> 182784
#define SM_H  182784                  // 26112 -> 208896
#define SM_B1 208896                  // 384
#define SM_B2 209280                  // 768
#define SM_XG 210048                  // 6144 -> 216192
#define DSZ   216192

__device__ __forceinline__ uint32_t smem_u32(const void* p) {
    uint32_t a;
    asm("{ .reg .u64 t; cvta.to.shared.u64 t, %1; cvt.u32.u64 %0, t; }" : "=r"(a) : "l"(p));
    return a;
}
__device__ __forceinline__ void ldsm4(uint32_t (&r)[4], uint32_t addr) {
    asm volatile("ldmatrix.sync.aligned.m8n8.x4.shared.b16 {%0,%1,%2,%3}, [%4];"
                 : "=r"(r[0]), "=r"(r[1]), "=r"(r[2]), "=r"(r[3]) : "r"(addr));
}
// x4 transposed: lanes 0-15 rows at px base, lanes 16-31 rows at px base+8
__device__ __forceinline__ void ldsm4t(uint32_t (&r)[4], uint32_t addr) {
    asm volatile("ldmatrix.sync.aligned.m8n8.x4.trans.shared.b16 {%0,%1,%2,%3}, [%4];"
                 : "=r"(r[0]), "=r"(r[1]), "=r"(r[2]), "=r"(r[3]) : "r"(addr));
}
// store 4x 8x8 b16 matrices; lane k supplies row addr of matrix k/8
__device__ __forceinline__ void stsm4(uint32_t addr, uint32_t r0, uint32_t r1,
                                      uint32_t r2, uint32_t r3) {
    asm volatile("stmatrix.sync.aligned.m8n8.x4.shared.b16 [%0], {%1,%2,%3,%4};"
                 :: "r"(addr), "r"(r0), "r"(r1), "r"(r2), "r"(r3) : "memory");
}
__device__ __forceinline__ void mma16816(float (&d)[4], const uint32_t (&a)[4],
                                         const uint32_t* b) {
    asm volatile("mma.sync.aligned.m16n8k16.row.col.f32.bf16.bf16.f32 "
                 "{%0,%1,%2,%3}, {%4,%5,%6,%7}, {%8,%9}, {%0,%1,%2,%3};"
                 : "+f"(d[0]), "+f"(d[1]), "+f"(d[2]), "+f"(d[3])
                 : "r"(a[0]), "r"(a[1]), "r"(a[2]), "r"(a[3]), "r"(b[0]), "r"(b[1]));
}
// sigmoid via single-MUFU tanh.approx: sigm(v) = 0.5 + 0.5*tanh(v/2)
__device__ __forceinline__ float sigm(float v) {
    float t;
    asm("tanh.approx.f32 %0, %1;" : "=f"(t) : "f"(0.5f * v));
    return fmaf(0.5f, t, 0.5f);
}
// exp(s), s in (0,1): e^0.5 * Taylor(u=s-0.5), rel err < 2e-5, FMA-only
__device__ __forceinline__ float exp01(float s) {
    float u = s - 0.5f;
    float p = 8.3333333e-3f;
    p = fmaf(p, u, 4.1666667e-2f);
    p = fmaf(p, u, 0.16666667f);
    p = fmaf(p, u, 0.5f);
    p = fmaf(p, u, 1.0f);
    p = fmaf(p, u, 1.0f);
    return 1.64872127f * p;
}

__device__ float g_gap[BATCH * 192];
__device__ float g_xg[BATCH * 192];

// ------------------------- GAP (MLP=16) -------------------------
__global__ void gap_kernel(const float* __restrict__ x1, const float* __restrict__ x2,
                           const float* __restrict__ x3) {
    int ch = blockIdx.x, b = blockIdx.y;
    const float* x = (ch < 64) ? x1 : (ch < 128) ? x2 : x3;
    const float* p = x + ((size_t)(b * 64 + (ch & 63))) * HWPX;
    int t4 = threadIdx.x * 4;
    float s0 = 0.f, s1 = 0.f, s2 = 0.f, s3 = 0.f;
#pragma unroll
    for (int i = 0; i < 4; i++) {
        float4 a = *(const float4*)(p + t4 + (i * 4 + 0) * 1024);
        float4 c = *(const float4*)(p + t4 + (i * 4 + 1) * 1024);
        float4 d = *(const float4*)(p + t4 + (i * 4 + 2) * 1024);
        float4 e = *(const float4*)(p + t4 + (i * 4 + 3) * 1024);
        s0 += (a.x + a.y) + (a.z + a.w);
        s1 += (c.x + c.y) + (c.z + c.w);
        s2 += (d.x + d.y) + (d.z + d.w);
        s3 += (e.x + e.y) + (e.z + e.w);
    }
    float s = (s0 + s1) + (s2 + s3);
#pragma unroll
    for (int off = 16; off; off >>= 1) s += __shfl_down_sync(0xFFFFFFFFu, s, off);
    __shared__ float sm[8];
    if ((threadIdx.x & 31) == 0) sm[threadIdx.x >> 5] = s;
    __syncthreads();
    if (threadIdx.x == 0) {
        float t = 0.f;
#pragma unroll
        for (int w = 0; w < 8; w++) t += sm[w];
        g_gap[b * 192 + ch] = t * (1.f / (float)HWPX);
    }
}

// ------------------------- global-branch MLP -------------------------
__global__ void gmlp_kernel(const float* __restrict__ gw1, const float* __restrict__ gb1,
                            const float* __restrict__ gg1, const float* __restrict__ gbe1,
                            const float* __restrict__ gm1, const float* __restrict__ gv1,
                            const float* __restrict__ gw2, const float* __restrict__ gb2,
                            const float* __restrict__ gg2, const float* __restrict__ gbe2,
                            const float* __restrict__ gm2, const float* __restrict__ gv2) {
    int b = blockIdx.x, t = threadIdx.x;
    __shared__ float v[192], h[96];
    v[t] = g_gap[b * 192 + t];
    __syncthreads();
    if (t < 96) {
        float a = gb1[t];
        const float* w = gw1 + t * 192;
#pragma unroll 4
        for (int c = 0; c < 192; c++) a = fmaf(w[c], v[c], a);
        float s = gg1[t] * rsqrtf(gv1[t] + EPSV);
        h[t] = fmaxf(fmaf(a - gm1[t], s, gbe1[t]), 0.f);
    }
    __syncthreads();
    {
        float a = gb2[t];
        const float* w = gw2 + t * 96;
#pragma unroll 4
        for (int c = 0; c < 96; c++) a = fmaf(w[c], h[c], a);
        float s = gg2[t] * rsqrtf(gv2[t] + EPSV);
        g_xg[b * 192 + t] = fmaf(a - gm2[t], s, gbe2[t]);
    }
}

// ------------------------- fused main kernel: 512 thr, 128-px tiles, X double-buffer ----
__global__ __launch_bounds__(NT, 1)
void main_kernel(const float* __restrict__ x1, const float* __restrict__ x2,
                 const float* __restrict__ x3,
                 const float* __restrict__ lw1, const float* __restrict__ lb1,
                 const float* __restrict__ lg1, const float* __restrict__ lbe1,
                 const float* __restrict__ lm1, const float* __restrict__ lv1,
                 const float* __restrict__ lw2, const float* __restrict__ lb2,
                 const float* __restrict__ lg2, const float* __restrict__ lbe2,
                 const float* __restrict__ lm2, const float* __restrict__ lv2,
                 float* __restrict__ out) {
    extern __shared__ char dsm[];
    const uint32_t SB = smem_u32(dsm);

    int tid = threadIdx.x;
    int wid = tid >> 5, lane = tid & 31;
    int qrow = lane >> 2;          // 0..7
    int qcol = lane & 3;           // 0..3
    int lsrow = lane & 15;
    int lscol = (lane >> 4) << 3;
    int s8 = wid & 7;              // px strip 0..7 (16 px each)
    int g  = wid >> 3;             // channel group 0..1
    int n0 = s8 << 4;
    int bofs = (lane >> 4) << 3;   // x4.trans px sub-offset (0 or 8)
    // stmatrix lane mapping: row within tile + px-half column offset
    int strow = (lane & 7) + ((lane >> 3) & 1) * 8;   // tile row 0..15
    int stpx  = (lane >> 4) << 3;                      // 0 or 8

    float* B1s = (float*)(dsm + SM_B1);
    float* B2s = (float*)(dsm + SM_B2);
    float* XGs = (float*)(dsm + SM_XG);

    // ---- prologue: fold BN into bf16 weights ----
    for (int i = tid; i < 96 * 192; i += NT) {
        int o = i / 192, k = i - o * 192;
        float sc = lg1[o] * rsqrtf(lv1[o] + EPSV);
        *(__nv_bfloat16*)(dsm + SM_W1 + (o * STW1 + k) * 2) = __float2bfloat16_rn(lw1[i] * sc);
        if (k == 0) B1s[o] = fmaf(lb1[o] - lm1[o], sc, lbe1[o]);
    }
    for (int i = tid; i < 192 * 96; i += NT) {
        int o = i / 96, k = i - o * 96;
        float sc = lg2[o] * rsqrtf(lv2[o] + EPSV);
        *(__nv_bfloat16*)(dsm + SM_W2 + (o * STW2 + k) * 2) = __float2bfloat16_rn(lw2[i] * sc);
        if (k == 0) B2s[o] = fmaf(lb2[o] - lm2[o], sc, lbe2[o]);
    }
    __syncthreads();
    for (int i = tid; i < BATCH * 192; i += NT) {
        int bb = i / 192;
        int c = i - bb * 192;
        XGs[i] = B2s[c] + g_xg[i];
    }

    const uint32_t W1S = SB + SM_W1, W2S = SB + SM_W2, HS = SB + SM_H;
    int px = lane << 2;   // this thread's pixel quad

    // ---- preload first tile into buffer 0 ----
    {
        int T0 = blockIdx.x;
        int b0 = T0 >> 7, hw00 = (T0 & 127) << 7;
#pragma unroll
        for (int j = 0; j < 12; j++) {
            int ch = wid + 16 * j;
            const float* xp = (ch < 64) ? x1 : (ch < 128) ? x2 : x3;
            float4 v = *(const float4*)(xp + ((size_t)((b0 << 6) + (ch & 63))) * HWPX + hw00 + px);
            __nv_bfloat162 p0 = __floats2bfloat162_rn(v.x, v.y);
            __nv_bfloat162 p1 = __floats2bfloat162_rn(v.z, v.w);
            *(uint2*)(dsm + SM_X0 + (ch * STX + px) * 2) =
                make_uint2(*(uint32_t*)&p0, *(uint32_t*)&p1);
        }
    }
    __syncthreads();

    int p = 0;
    for (int T = blockIdx.x; T < NTILES; T += NCTA) {
        int b = T >> 7;
        int hw0 = (T & 127) << 7;
        const float* XGb = XGs + b * 192;
        const uint32_t xoff  = p ? SM_X1 : SM_X0;
        const uint32_t xoffn = p ? SM_X0 : SM_X1;
        const uint32_t XS = SB + xoff;

        // ---- prefetch NEXT tile's X into regs (latency hidden by GEMM1) ----
        int Tn = T + NCTA;
        bool hasNext = Tn < NTILES;
        int Tc = hasNext ? Tn : T;
        int bn = Tc >> 7, hwn = (Tc & 127) << 7;
        float4 xn[12];
#pragma unroll
        for (int j = 0; j < 12; j++) {
            int ch = wid + 16 * j;
            const float* xp = (ch < 64) ? x1 : (ch < 128) ? x2 : x3;
            xn[j] = *(const float4*)(xp + ((size_t)((bn << 6) + (ch & 63))) * HWPX + hwn + px);
        }

        // ---- GEMM1: warp (s8,g): C1[48ch of group g][16px strip], K=192 ----
        float acc1[3][2][4];
#pragma unroll
        for (int mi = 0; mi < 3; mi++)
#pragma unroll
            for (int nf = 0; nf < 2; nf++)
#pragma unroll
                for (int i = 0; i < 4; i++) acc1[mi][nf][i] = 0.f;
#pragma unroll
        for (int kt = 0; kt < 12; kt++) {
            uint32_t bf[4];   // {b0[0],b0[1],b1[0],b1[1]} via one x4.trans
            ldsm4t(bf, XS + ((16 * kt + lsrow) * STX + n0 + bofs) * 2);
#pragma unroll
            for (int mi = 0; mi < 3; mi++) {
                uint32_t a[4];
                ldsm4(a, W1S + ((16 * (3 * g + mi) + lsrow) * STW1 + 16 * kt + lscol) * 2);
                mma16816(acc1[mi][0], a, bf);
                mma16816(acc1[mi][1], a, bf + 2);
            }
        }

        // ---- epilogue1: bias + relu -> Hs via stmatrix (1 store per 16x16 tile) ----
#pragma unroll
        for (int mi = 0; mi < 3; mi++) {
            int ca = 16 * (3 * g + mi);
            float ba = B1s[ca + qrow], bb = B1s[ca + 8 + qrow];
            __nv_bfloat162 t0 = __floats2bfloat162_rn(fmaxf(acc1[mi][0][0] + ba, 0.f),
                                                      fmaxf(acc1[mi][0][1] + ba, 0.f));
            __nv_bfloat162 t1 = __floats2bfloat162_rn(fmaxf(acc1[mi][0][2] + bb, 0.f),
                                                      fmaxf(acc1[mi][0][3] + bb, 0.f));
            __nv_bfloat162 t2 = __floats2bfloat162_rn(fmaxf(acc1[mi][1][0] + ba, 0.f),
                                                      fmaxf(acc1[mi][1][1] + ba, 0.f));
            __nv_bfloat162 t3 = __floats2bfloat162_rn(fmaxf(acc1[mi][1][2] + bb, 0.f),
                                                      fmaxf(acc1[mi][1][3] + bb, 0.f));
            uint32_t addr = HS + ((ca + strow) * STH + n0 + stpx) * 2;
            stsm4(addr, *(uint32_t*)&t0, *(uint32_t*)&t1, *(uint32_t*)&t2, *(uint32_t*)&t3);
        }

        // ---- store prefetched next tile into the dead alternate buffer ----
        if (hasNext) {
#pragma unroll
            for (int j = 0; j < 12; j++) {
                int ch = wid + 16 * j;
                __nv_bfloat162 p0 = __floats2bfloat162_rn(xn[j].x, xn[j].y);
                __nv_bfloat162 p1 = __floats2bfloat162_rn(xn[j].z, xn[j].w);
                *(uint2*)(dsm + xoffn + (ch * STX + px) * 2) =
                    make_uint2(*(uint32_t*)&p0, *(uint32_t*)&p1);
            }
        }

        // pair barrier: H strip s8 produced/consumed only by warps (s8,0),(s8,1)
        asm volatile("bar.sync %0, %1;" :: "r"(s8 + 1), "r"(64) : "memory");

        // ---- GEMM2: warp (s8,g): 6 m-tiles (triples of [32g,32g+32)), K=96 ----
        float acc2[6][2][4];
#pragma unroll
        for (int i6 = 0; i6 < 6; i6++)
#pragma unroll
            for (int nf = 0; nf < 2; nf++)
#pragma unroll
                for (int i = 0; i < 4; i++) acc2[i6][nf][i] = 0.f;
#pragma unroll
        for (int kt = 0; kt < 6; kt++) {
            uint32_t hf[4];
            ldsm4t(hf, HS + ((16 * kt + lsrow) * STH + n0 + bofs) * 2);
#pragma unroll
            for (int i6 = 0; i6 < 6; i6++) {
                int mt = 4 * (i6 >> 1) + 2 * g + (i6 & 1);
                uint32_t a[4];
                ldsm4(a, W2S + ((16 * mt + lsrow) * STW2 + 16 * kt + lscol) * 2);
                mma16816(acc2[i6][0], a, hf);
                mma16816(acc2[i6][1], a, hf + 2);
            }
        }

        // ---- prefetch current-tile x for combine (coalesced, L2-resident) ----
        float4 xv[12];
#pragma unroll
        for (int j = 0; j < 12; j++) {
            int ch = wid + 16 * j;
            const float* xp = (ch < 64) ? x1 : (ch < 128) ? x2 : x3;
            xv[j] = *(const float4*)(xp + ((size_t)((b << 6) + (ch & 63))) * HWPX + hw0 + px);
        }

        // ---- epilogue2: sigmoid -> S fp16 via stmatrix (aliases CURRENT X buf) ----
#pragma unroll
        for (int i6 = 0; i6 < 6; i6++) {
            int mt = 4 * (i6 >> 1) + 2 * g + (i6 & 1);
            int cb = 16 * mt;
            float base0 = XGb[cb + qrow], base1 = XGb[cb + 8 + qrow];
            __half2 t0 = __floats2half2_rn(sigm(acc2[i6][0][0] + base0),
                                           sigm(acc2[i6][0][1] + base0));
            __half2 t1 = __floats2half2_rn(sigm(acc2[i6][0][2] + base1),
                                           sigm(acc2[i6][0][3] + base1));
            __half2 t2 = __floats2half2_rn(sigm(acc2[i6][1][0] + base0),
                                           sigm(acc2[i6][1][1] + base0));
            __half2 t3 = __floats2half2_rn(sigm(acc2[i6][1][2] + base1),
                                           sigm(acc2[i6][1][3] + base1));
            uint32_t addr = SB + xoff + ((cb + strow) * STX + n0 + stpx) * 2;
            stsm4(addr, *(uint32_t*)&t0, *(uint32_t*)&t1, *(uint32_t*)&t2, *(uint32_t*)&t3);
        }
        __syncthreads();

        // ---- combine: x from prefetched regs, S from smem, coalesced float4 STG ----
#pragma unroll
        for (int a = 0; a < 4; a++) {
            int c = wid + 16 * a;   // 0..63
            uint2 rA = *(const uint2*)(dsm + xoff + (c * STX + px) * 2);
            uint2 rB = *(const uint2*)(dsm + xoff + ((c + 64) * STX + px) * 2);
            uint2 rC = *(const uint2*)(dsm + xoff + ((c + 128) * STX + px) * 2);
            float2 a01 = __half22float2(*(__half2*)&rA.x);
            float2 a23 = __half22float2(*(__half2*)&rA.y);
            float2 b01 = __half22float2(*(__half2*)&rB.x);
            float2 b23 = __half22float2(*(__half2*)&rB.y);
            float2 c01 = __half22float2(*(__half2*)&rC.x);
            float2 c23 = __half22float2(*(__half2*)&rC.y);
            float sa[4] = {a01.x, a01.y, a23.x, a23.y};
            float sb[4] = {b01.x, b01.y, b23.x, b23.y};
            float sc[4] = {c01.x, c01.y, c23.x, c23.y};
            float xa[4] = {xv[a].x, xv[a].y, xv[a].z, xv[a].w};
            float xb[4] = {xv[a + 4].x, xv[a + 4].y, xv[a + 4].z, xv[a + 4].w};
            float xc[4] = {xv[a + 8].x, xv[a + 8].y, xv[a + 8].z, xv[a + 8].w};
            float r[4];
#pragma unroll
            for (int k = 0; k < 4; k++) {
                float e0 = exp01(sa[k]), e1 = exp01(sb[k]), e2 = exp01(sc[k]);
                float inv = __fdividef(1.f, e0 + e1 + e2);
                r[k] = (e0 * xa[k] + e1 * xb[k] + e2 * xc[k]) * inv;
            }
            *(float4*)(out + ((size_t)((b << 6) + c)) * HWPX + hw0 + px) =
                make_float4(r[0], r[1], r[2], r[3]);
        }
        __syncthreads();
        p ^= 1;
    }
}

extern "C" void kernel_launch(void* const* d_in, const int* in_sizes, int n_in,
                              void* d_out, int out_size) {
    const float* x1 = (const float*)d_in[0];
    const float* x2 = (const float*)d_in[1];
    const float* x3 = (const float*)d_in[2];
    const float* lw1 = (const float*)d_in[3];
    const float* lb1 = (const float*)d_in[4];
    const float* lg1 = (const float*)d_in[5];
    const float* lbe1 = (const float*)d_in[6];
    const float* lm1 = (const float*)d_in[7];
    const float* lv1 = (const float*)d_in[8];
    const float* lw2 = (const float*)d_in[9];
    const float* lb2 = (const float*)d_in[10];
    const float* lg2 = (const float*)d_in[11];
    const float* lbe2 = (const float*)d_in[12];
    const float* lm2 = (const float*)d_in[13];
    const float* lv2 = (const float*)d_in[14];
    const float* gw1 = (const float*)d_in[15];
    const float* gb1 = (const float*)d_in[16];
    const float* gg1 = (const float*)d_in[17];
    const float* gbe1 = (const float*)d_in[18];
    const float* gm1 = (const float*)d_in[19];
    const float* gv1 = (const float*)d_in[20];
    const float* gw2 = (const float*)d_in[21];
    const float* gb2 = (const float*)d_in[22];
    const float* gg2 = (const float*)d_in[23];
    const float* gbe2 = (const float*)d_in[24];
    const float* gm2 = (const float*)d_in[25];
    const float* gv2 = (const float*)d_in[26];
    float* out = (float*)d_out;

    cudaFuncSetAttribute(main_kernel, cudaFuncAttributeMaxDynamicSharedMemorySize, DSZ);

    gap_kernel<<<dim3(192, BATCH), 256>>>(x1, x2, x3);
    gmlp_kernel<<<BATCH, 192>>>(gw1, gb1, gg1, gbe1, gm1, gv1,
                                gw2, gb2, gg2, gbe2, gm2, gv2);
    main_kernel<<<NCTA, NT, DSZ>>>(x1, x2, x3,
                                   lw1, lb1, lg1, lbe1, lm1, lv1,
                                   lw2, lb2, lg2, lbe2, lm2, lv2, out);
}